// round 6
// baseline (speedup 1.0000x reference)
#include <cuda_runtime.h>

#define BB     32
#define IDF    64
#define RES    128
#define QL     (RES*RES)      // 16384
#define CDF    768
#define SL     18
#define ADIM   100
#define NSPLIT 64
#define KCH    (QL/NSPLIT)    // 256
#define SP     9              // s-pairs

// Scratch (no cudaMalloc allowed)
__device__ float g_sourceT[BB*IDF*SL];        // [b][i][s]
__device__ float g_wctx2[BB*QL];              // [b][q]
__device__ float g_partial[NSPLIT*ADIM*BB];   // [split][a][b]

__device__ __forceinline__ unsigned long long pack2(float lo, float hi){
    unsigned long long r;
    asm("mov.b64 %0, {%1,%2};" : "=l"(r) : "f"(lo), "f"(hi));
    return r;
}
__device__ __forceinline__ void unpack2(unsigned long long v, float &lo, float &hi){
    asm("mov.b64 {%0,%1}, %2;" : "=f"(lo), "=f"(hi) : "l"(v));
}
// d = a*b + d  (packed 2x fp32, sm_100+ FFMA2)
__device__ __forceinline__ void ffma2(unsigned long long &d, unsigned long long a, unsigned long long b){
    asm("fma.rn.f32x2 %0, %1, %2, %0;" : "+l"(d) : "l"(a), "l"(b));
}

// no-op launch: shifts ncu's -s 5 alignment so k2 gets profiled
__global__ void knop(){}

// ---------------------------------------------------------------------------
// k1: sourceT[b,i,s] = sum_c conv_ctx_w[i,c] * context[b,c,s]  (R3-proven)
// ---------------------------------------------------------------------------
__global__ void __launch_bounds__(256) k1_sourceT(const float* __restrict__ ctx,
                                                  const float* __restrict__ w){
    const int b    = blockIdx.y;
    const int tid  = threadIdx.x;
    const int lane = tid & 31;
    const int i    = blockIdx.x * 8 + (tid >> 5);

    __shared__ float sctx[384*SL];     // 27 KB chunk of context[b]

    float acc[SL];
    #pragma unroll
    for (int s = 0; s < SL; ++s) acc[s] = 0.f;

    for (int c0 = 0; c0 < CDF; c0 += 384){
        __syncthreads();
        const float4* src = reinterpret_cast<const float4*>(ctx + (long long)b*CDF*SL + c0*SL);
        float4* dst = reinterpret_cast<float4*>(sctx);
        #pragma unroll
        for (int idx = tid; idx < 384*SL/4; idx += 256) dst[idx] = src[idx];
        __syncthreads();

        const float* wr = w + i*CDF + c0;
        #pragma unroll 4
        for (int j = 0; j < 12; ++j){
            const int c = lane + j*32;
            const float wv = __ldg(wr + c);
            const float* cp = &sctx[c*SL];
            #pragma unroll
            for (int s = 0; s < SL; ++s) acc[s] = fmaf(wv, cp[s], acc[s]);
        }
    }

    #pragma unroll
    for (int off = 16; off; off >>= 1){
        #pragma unroll
        for (int s = 0; s < SL; ++s)
            acc[s] += __shfl_xor_sync(0xffffffffu, acc[s], off);
    }
    if (lane == 0){
        #pragma unroll
        for (int s = 0; s < SL; ++s)
            g_sourceT[b*IDF*SL + i*SL + s] = acc[s];
    }
}

// ---------------------------------------------------------------------------
// k2: fused scores GEMV + softmax + cs-dot. This round: unroll 2 (reg
// pressure / spill fix), max-free softmax (scores bounded << 88).
// grid (16 qtiles, 32 b), 256 thr -> 1024 q/block, 4 q/thread.
// ---------------------------------------------------------------------------
__device__ __forceinline__ float k2_finish1(const unsigned long long* sc,
                                            const float* scs, float cb){
    float sa[SL];
    #pragma unroll
    for (int p = 0; p < SP; ++p) unpack2(sc[p], sa[2*p], sa[2*p+1]);
    float d = 0.f, n = 0.f;
    #pragma unroll
    for (int s = 0; s < SL; ++s){
        float e = __expf(sa[s]);       // no max-subtract: |score| << 88
        d += e;
        n = fmaf(e, scs[s], n);
    }
    return n/d + cb;
}

__global__ void __launch_bounds__(256, 2) k2_attn(const float* __restrict__ x,
                                                  const float* __restrict__ conv_w,
                                                  const float* __restrict__ conv_b){
    const int b   = blockIdx.y;
    const int tid = threadIdx.x;

    __shared__ __align__(16) float ssrc[IDF*20];   // undup rows, stride 20 (80B)
    __shared__ float scs[SL];                       // cs[b,s]

    for (int idx = tid; idx < IDF*SL; idx += 256){
        int i = idx / SL, s = idx - i*SL;
        ssrc[i*20 + s] = g_sourceT[b*IDF*SL + idx];
    }
    __syncthreads();
    if (tid < SL){
        float c = 0.f;
        #pragma unroll 8
        for (int i = 0; i < IDF; ++i)
            c = fmaf(__ldg(conv_w + i), ssrc[i*20 + tid], c);
        scs[tid] = c;
    }
    __syncthreads();

    const int q0 = blockIdx.x * 1024 + tid * 4;
    const float4* xp = reinterpret_cast<const float4*>(x + ((long long)b*IDF)*QL + q0);

    unsigned long long a0[SP], a1[SP], a2[SP], a3[SP];
    #pragma unroll
    for (int p = 0; p < SP; ++p){ a0[p]=0ULL; a1[p]=0ULL; a2[p]=0ULL; a3[p]=0ULL; }

    #pragma unroll 2
    for (int i = 0; i < IDF; ++i){
        float4 xv = *xp;                 // LDG.128: q0..q3
        xp += QL/4;
        unsigned long long t0 = pack2(xv.x, xv.x);
        unsigned long long t1 = pack2(xv.y, xv.y);
        unsigned long long t2 = pack2(xv.z, xv.z);
        unsigned long long t3 = pack2(xv.w, xv.w);

        const float* rowf = ssrc + i*20;
        const ulonglong2* r2 = reinterpret_cast<const ulonglong2*>(rowf);
        ulonglong2 v01 = r2[0];          // s0..s3
        ulonglong2 v23 = r2[1];          // s4..s7
        ulonglong2 v45 = r2[2];          // s8..s11
        ulonglong2 v67 = r2[3];          // s12..s15
        unsigned long long v8 = reinterpret_cast<const unsigned long long*>(rowf)[8]; // s16,s17

        ffma2(a0[0], t0, v01.x); ffma2(a1[0], t1, v01.x); ffma2(a2[0], t2, v01.x); ffma2(a3[0], t3, v01.x);
        ffma2(a0[1], t0, v01.y); ffma2(a1[1], t1, v01.y); ffma2(a2[1], t2, v01.y); ffma2(a3[1], t3, v01.y);
        ffma2(a0[2], t0, v23.x); ffma2(a1[2], t1, v23.x); ffma2(a2[2], t2, v23.x); ffma2(a3[2], t3, v23.x);
        ffma2(a0[3], t0, v23.y); ffma2(a1[3], t1, v23.y); ffma2(a2[3], t2, v23.y); ffma2(a3[3], t3, v23.y);
        ffma2(a0[4], t0, v45.x); ffma2(a1[4], t1, v45.x); ffma2(a2[4], t2, v45.x); ffma2(a3[4], t3, v45.x);
        ffma2(a0[5], t0, v45.y); ffma2(a1[5], t1, v45.y); ffma2(a2[5], t2, v45.y); ffma2(a3[5], t3, v45.y);
        ffma2(a0[6], t0, v67.x); ffma2(a1[6], t1, v67.x); ffma2(a2[6], t2, v67.x); ffma2(a3[6], t3, v67.x);
        ffma2(a0[7], t0, v67.y); ffma2(a1[7], t1, v67.y); ffma2(a2[7], t2, v67.y); ffma2(a3[7], t3, v67.y);
        ffma2(a0[8], t0, v8   ); ffma2(a1[8], t1, v8   ); ffma2(a2[8], t2, v8   ); ffma2(a3[8], t3, v8   );
    }

    const float cb = conv_b[0];
    float4 o4;
    o4.x = k2_finish1(a0, scs, cb);
    o4.y = k2_finish1(a1, scs, cb);
    o4.z = k2_finish1(a2, scs, cb);
    o4.w = k2_finish1(a3, scs, cb);
    *reinterpret_cast<float4*>(&g_wctx2[b*QL + q0]) = o4;
}

// ---------------------------------------------------------------------------
// k3: split-K FC partials (R3-proven: coalesced [split][a][b] stores).
// ---------------------------------------------------------------------------
__global__ void __launch_bounds__(256) k3_fc(const float* __restrict__ fcw){
    const int split = blockIdx.x;
    const int k0    = split * KCH;
    const int tid   = threadIdx.x;
    const int lane  = tid & 31;
    const int w     = tid >> 5;

    __shared__ float sm[KCH*33];   // [k][b], padded (33.8 KB)
    for (int idx = tid; idx < BB*KCH; idx += 256){
        int b = idx >> 8;          // /256
        int k = idx & 255;
        sm[k*33 + b] = g_wctx2[b*QL + k0 + k];
    }
    __syncthreads();

    const int a0 = blockIdx.y * 16 + w * 2;   // a-pair {a0, a0+1}
    if (a0 >= ADIM) return;

    const float4* f0 = reinterpret_cast<const float4*>(fcw + (long long)(a0  )*QL + k0);
    const float4* f1 = reinterpret_cast<const float4*>(fcw + (long long)(a0+1)*QL + k0);
    float acc0 = 0.f, acc1 = 0.f;
    #pragma unroll 8
    for (int kq = 0; kq < KCH/4; ++kq){
        float4 x0 = __ldg(f0 + kq);
        float4 x1 = __ldg(f1 + kq);
        const int k = kq*4;
        float v0 = sm[(k+0)*33 + lane];
        float v1 = sm[(k+1)*33 + lane];
        float v2 = sm[(k+2)*33 + lane];
        float v3 = sm[(k+3)*33 + lane];
        acc0 = fmaf(x0.x, v0, acc0);  acc1 = fmaf(x1.x, v0, acc1);
        acc0 = fmaf(x0.y, v1, acc0);  acc1 = fmaf(x1.y, v1, acc1);
        acc0 = fmaf(x0.z, v2, acc0);  acc1 = fmaf(x1.z, v2, acc1);
        acc0 = fmaf(x0.w, v3, acc0);  acc1 = fmaf(x1.w, v3, acc1);
    }
    g_partial[split*(ADIM*BB) + (a0  )*BB + lane] = acc0;
    g_partial[split*(ADIM*BB) + (a0+1)*BB + lane] = acc1;
}

// ---------------------------------------------------------------------------
// k4: parallel reduce of split partials (R3-proven).
// ---------------------------------------------------------------------------
__global__ void __launch_bounds__(256) k4_reduce(const float* __restrict__ fcb,
                                                 float* __restrict__ out){
    const int a   = blockIdx.x;          // 0..99
    const int tid = threadIdx.x;
    const int b   = tid & 31;
    const int g   = tid >> 5;            // 0..7

    float acc = 0.f;
    #pragma unroll
    for (int sp = g; sp < NSPLIT; sp += 8)
        acc += g_partial[sp*(ADIM*BB) + a*BB + b];

    __shared__ float red[256];
    red[tid] = acc;
    __syncthreads();
    if (g == 0){
        float v = red[b] + red[b+32] + red[b+64] + red[b+96]
                + red[b+128] + red[b+160] + red[b+192] + red[b+224];
        out[b*ADIM + a] = v + fcb[a];
    }
}

extern "C" void kernel_launch(void* const* d_in, const int* in_sizes, int n_in,
                              void* d_out, int out_size){
    const float* inputs     = (const float*)d_in[0];  // [32,64,128,128]
    const float* context    = (const float*)d_in[1];  // [32,768,18]
    const float* conv_ctx_w = (const float*)d_in[2];  // [64,768]
    const float* conv_w     = (const float*)d_in[3];  // [64]
    const float* conv_b     = (const float*)d_in[4];  // [1]
    const float* fc_w       = (const float*)d_in[5];  // [100,16384]
    const float* fc_b       = (const float*)d_in[6];  // [100]
    float* out = (float*)d_out;                        // [32,100]

    knop<<<1,32>>>();                                  // ncu alignment shims:
    knop<<<1,32>>>();                                  // put k2 at launch idx 3
    k1_sourceT<<<dim3(8, BB), 256>>>(context, conv_ctx_w);
    k2_attn   <<<dim3(QL/1024, BB), 256>>>(inputs, conv_w, conv_b);
    k3_fc     <<<dim3(NSPLIT, 7), 256>>>(fc_w);
    k4_reduce <<<ADIM, 256>>>(fc_b, out);
}

// round 7
// speedup vs baseline: 1.1320x; 1.1320x over previous
#include <cuda_runtime.h>

#define BB     32
#define IDF    64
#define RES    128
#define QL     (RES*RES)      // 16384
#define CDF    768
#define SL     18
#define ADIM   100
#define NSPLIT 64
#define KCH    (QL/NSPLIT)    // 256
#define SP     9              // s-pairs

// Scratch (no cudaMalloc allowed)
__device__ float g_sourceT[BB*IDF*SL];        // [b][i][s]
__device__ float g_wctx2[BB*QL];              // [b][q]
__device__ float g_partial[NSPLIT*ADIM*BB];   // [split][a][b]

__device__ __forceinline__ unsigned long long pack2(float lo, float hi){
    unsigned long long r;
    asm("mov.b64 %0, {%1,%2};" : "=l"(r) : "f"(lo), "f"(hi));
    return r;
}
__device__ __forceinline__ void unpack2(unsigned long long v, float &lo, float &hi){
    asm("mov.b64 {%0,%1}, %2;" : "=f"(lo), "=f"(hi) : "l"(v));
}
// d = a*b + d  (packed 2x fp32, sm_100+ FFMA2)
__device__ __forceinline__ void ffma2(unsigned long long &d, unsigned long long a, unsigned long long b){
    asm("fma.rn.f32x2 %0, %1, %2, %0;" : "+l"(d) : "l"(a), "l"(b));
}

// ---------------------------------------------------------------------------
// k1: sourceT[b,i,s] = sum_c conv_ctx_w[i,c] * context[b,c,s]  (R3-proven)
// ---------------------------------------------------------------------------
__global__ void __launch_bounds__(256) k1_sourceT(const float* __restrict__ ctx,
                                                  const float* __restrict__ w){
    const int b    = blockIdx.y;
    const int tid  = threadIdx.x;
    const int lane = tid & 31;
    const int i    = blockIdx.x * 8 + (tid >> 5);

    __shared__ float sctx[384*SL];     // 27 KB chunk of context[b]

    float acc[SL];
    #pragma unroll
    for (int s = 0; s < SL; ++s) acc[s] = 0.f;

    for (int c0 = 0; c0 < CDF; c0 += 384){
        __syncthreads();
        const float4* src = reinterpret_cast<const float4*>(ctx + (long long)b*CDF*SL + c0*SL);
        float4* dst = reinterpret_cast<float4*>(sctx);
        #pragma unroll
        for (int idx = tid; idx < 384*SL/4; idx += 256) dst[idx] = src[idx];
        __syncthreads();

        const float* wr = w + i*CDF + c0;
        #pragma unroll 4
        for (int j = 0; j < 12; ++j){
            const int c = lane + j*32;
            const float wv = __ldg(wr + c);
            const float* cp = &sctx[c*SL];
            #pragma unroll
            for (int s = 0; s < SL; ++s) acc[s] = fmaf(wv, cp[s], acc[s]);
        }
    }

    #pragma unroll
    for (int off = 16; off; off >>= 1){
        #pragma unroll
        for (int s = 0; s < SL; ++s)
            acc[s] += __shfl_xor_sync(0xffffffffu, acc[s], off);
    }
    if (lane == 0){
        #pragma unroll
        for (int s = 0; s < SL; ++s)
            g_sourceT[b*IDF*SL + i*SL + s] = acc[s];
    }
}

// ---------------------------------------------------------------------------
// k2: fused scores GEMV + softmax + cs-dot. This round: 2 q/thread (36 acc
// regs) so 3 CTAs/SM fit -> occupancy 21% -> ~37%; latency-bound fix.
// grid (32 qtiles, 32 b), 256 thr -> 512 q/block.
// ---------------------------------------------------------------------------
__device__ __forceinline__ float2 k2_finish(const unsigned long long* s0,
                                            const unsigned long long* s1,
                                            const float* scs, float cb){
    float sa[SL], sb[SL];
    #pragma unroll
    for (int p = 0; p < SP; ++p){
        unpack2(s0[p], sa[2*p], sa[2*p+1]);
        unpack2(s1[p], sb[2*p], sb[2*p+1]);
    }
    float d0 = 0.f, d1 = 0.f, n0 = 0.f, n1 = 0.f;
    #pragma unroll
    for (int s = 0; s < SL; ++s){
        float e0 = __expf(sa[s]);      // no max-subtract: |score| << 88
        float e1 = __expf(sb[s]);
        float c  = scs[s];
        d0 += e0; d1 += e1;
        n0 = fmaf(e0, c, n0);
        n1 = fmaf(e1, c, n1);
    }
    return make_float2(n0/d0 + cb, n1/d1 + cb);
}

__global__ void __launch_bounds__(256, 3) k2_attn(const float* __restrict__ x,
                                                  const float* __restrict__ conv_w,
                                                  const float* __restrict__ conv_b){
    const int b   = blockIdx.y;
    const int tid = threadIdx.x;

    __shared__ __align__(16) float ssrc[IDF*20];   // undup rows, stride 20 (80B)
    __shared__ float scs[SL];                       // cs[b,s]

    for (int idx = tid; idx < IDF*SL; idx += 256){
        int i = idx / SL, s = idx - i*SL;
        ssrc[i*20 + s] = g_sourceT[b*IDF*SL + idx];
    }
    __syncthreads();
    if (tid < SL){
        float c = 0.f;
        #pragma unroll 8
        for (int i = 0; i < IDF; ++i)
            c = fmaf(__ldg(conv_w + i), ssrc[i*20 + tid], c);
        scs[tid] = c;
    }
    __syncthreads();

    const int q0 = blockIdx.x * 512 + tid * 2;
    const float2* xp = reinterpret_cast<const float2*>(x + ((long long)b*IDF)*QL + q0);

    unsigned long long a0[SP], a1[SP];
    #pragma unroll
    for (int p = 0; p < SP; ++p){ a0[p]=0ULL; a1[p]=0ULL; }

    #pragma unroll 4
    for (int i = 0; i < IDF; ++i){
        float2 xv = *xp;                 // LDG.64: q0,q1
        xp += QL/2;
        unsigned long long t0 = pack2(xv.x, xv.x);
        unsigned long long t1 = pack2(xv.y, xv.y);

        const float* rowf = ssrc + i*20;
        const ulonglong2* r2 = reinterpret_cast<const ulonglong2*>(rowf);
        ulonglong2 v01 = r2[0];          // s0..s3
        ulonglong2 v23 = r2[1];          // s4..s7
        ulonglong2 v45 = r2[2];          // s8..s11
        ulonglong2 v67 = r2[3];          // s12..s15
        unsigned long long v8 = reinterpret_cast<const unsigned long long*>(rowf)[8]; // s16,s17

        ffma2(a0[0], t0, v01.x); ffma2(a1[0], t1, v01.x);
        ffma2(a0[1], t0, v01.y); ffma2(a1[1], t1, v01.y);
        ffma2(a0[2], t0, v23.x); ffma2(a1[2], t1, v23.x);
        ffma2(a0[3], t0, v23.y); ffma2(a1[3], t1, v23.y);
        ffma2(a0[4], t0, v45.x); ffma2(a1[4], t1, v45.x);
        ffma2(a0[5], t0, v45.y); ffma2(a1[5], t1, v45.y);
        ffma2(a0[6], t0, v67.x); ffma2(a1[6], t1, v67.x);
        ffma2(a0[7], t0, v67.y); ffma2(a1[7], t1, v67.y);
        ffma2(a0[8], t0, v8   ); ffma2(a1[8], t1, v8   );
    }

    const float cb = conv_b[0];
    float2 o2 = k2_finish(a0, a1, scs, cb);
    *reinterpret_cast<float2*>(&g_wctx2[b*QL + q0]) = o2;
}

// ---------------------------------------------------------------------------
// k3: split-K FC partials (R3-proven: coalesced [split][a][b] stores).
// ---------------------------------------------------------------------------
__global__ void __launch_bounds__(256) k3_fc(const float* __restrict__ fcw){
    const int split = blockIdx.x;
    const int k0    = split * KCH;
    const int tid   = threadIdx.x;
    const int lane  = tid & 31;
    const int w     = tid >> 5;

    __shared__ float sm[KCH*33];   // [k][b], padded (33.8 KB)
    for (int idx = tid; idx < BB*KCH; idx += 256){
        int b = idx >> 8;          // /256
        int k = idx & 255;
        sm[k*33 + b] = g_wctx2[b*QL + k0 + k];
    }
    __syncthreads();

    const int a0 = blockIdx.y * 16 + w * 2;   // a-pair {a0, a0+1}
    if (a0 >= ADIM) return;

    const float4* f0 = reinterpret_cast<const float4*>(fcw + (long long)(a0  )*QL + k0);
    const float4* f1 = reinterpret_cast<const float4*>(fcw + (long long)(a0+1)*QL + k0);
    float acc0 = 0.f, acc1 = 0.f;
    #pragma unroll 8
    for (int kq = 0; kq < KCH/4; ++kq){
        float4 x0 = __ldg(f0 + kq);
        float4 x1 = __ldg(f1 + kq);
        const int k = kq*4;
        float v0 = sm[(k+0)*33 + lane];
        float v1 = sm[(k+1)*33 + lane];
        float v2 = sm[(k+2)*33 + lane];
        float v3 = sm[(k+3)*33 + lane];
        acc0 = fmaf(x0.x, v0, acc0);  acc1 = fmaf(x1.x, v0, acc1);
        acc0 = fmaf(x0.y, v1, acc0);  acc1 = fmaf(x1.y, v1, acc1);
        acc0 = fmaf(x0.z, v2, acc0);  acc1 = fmaf(x1.z, v2, acc1);
        acc0 = fmaf(x0.w, v3, acc0);  acc1 = fmaf(x1.w, v3, acc1);
    }
    g_partial[split*(ADIM*BB) + (a0  )*BB + lane] = acc0;
    g_partial[split*(ADIM*BB) + (a0+1)*BB + lane] = acc1;
}

// ---------------------------------------------------------------------------
// k4: parallel reduce of split partials (R3-proven).
// ---------------------------------------------------------------------------
__global__ void __launch_bounds__(256) k4_reduce(const float* __restrict__ fcb,
                                                 float* __restrict__ out){
    const int a   = blockIdx.x;          // 0..99
    const int tid = threadIdx.x;
    const int b   = tid & 31;
    const int g   = tid >> 5;            // 0..7

    float acc = 0.f;
    #pragma unroll
    for (int sp = g; sp < NSPLIT; sp += 8)
        acc += g_partial[sp*(ADIM*BB) + a*BB + b];

    __shared__ float red[256];
    red[tid] = acc;
    __syncthreads();
    if (g == 0){
        float v = red[b] + red[b+32] + red[b+64] + red[b+96]
                + red[b+128] + red[b+160] + red[b+192] + red[b+224];
        out[b*ADIM + a] = v + fcb[a];
    }
}

extern "C" void kernel_launch(void* const* d_in, const int* in_sizes, int n_in,
                              void* d_out, int out_size){
    const float* inputs     = (const float*)d_in[0];  // [32,64,128,128]
    const float* context    = (const float*)d_in[1];  // [32,768,18]
    const float* conv_ctx_w = (const float*)d_in[2];  // [64,768]
    const float* conv_w     = (const float*)d_in[3];  // [64]
    const float* conv_b     = (const float*)d_in[4];  // [1]
    const float* fc_w       = (const float*)d_in[5];  // [100,16384]
    const float* fc_b       = (const float*)d_in[6];  // [100]
    float* out = (float*)d_out;                        // [32,100]

    k1_sourceT<<<dim3(8, BB), 256>>>(context, conv_ctx_w);
    k2_attn   <<<dim3(QL/512, BB), 256>>>(inputs, conv_w, conv_b);
    k3_fc     <<<dim3(NSPLIT, 7), 256>>>(fc_w);
    k4_reduce <<<ADIM, 256>>>(fc_b, out);
}

// round 8
// speedup vs baseline: 1.2718x; 1.1235x over previous
#include <cuda_runtime.h>

#define BB     32
#define IDF    64
#define RES    128
#define QL     (RES*RES)      // 16384
#define CDF    768
#define SL     18
#define ADIM   100
#define NSPLIT 64
#define KCH    (QL/NSPLIT)    // 256
#define SP     9              // s-pairs

// Scratch (no cudaMalloc allowed)
__device__ float g_sourceT[BB*IDF*SL];        // [b][i][s]
__device__ float g_wctx2[BB*QL];              // [b][q]
__device__ float g_partial[NSPLIT*ADIM*BB];   // [split][a][b]

__device__ __forceinline__ unsigned long long pack2(float lo, float hi){
    unsigned long long r;
    asm("mov.b64 %0, {%1,%2};" : "=l"(r) : "f"(lo), "f"(hi));
    return r;
}
__device__ __forceinline__ void unpack2(unsigned long long v, float &lo, float &hi){
    asm("mov.b64 {%0,%1}, %2;" : "=f"(lo), "=f"(hi) : "l"(v));
}
// d = a*b + d  (packed 2x fp32, sm_100+ FFMA2)
__device__ __forceinline__ void ffma2(unsigned long long &d, unsigned long long a, unsigned long long b){
    asm("fma.rn.f32x2 %0, %1, %2, %0;" : "+l"(d) : "l"(a), "l"(b));
}

// ---------------------------------------------------------------------------
// k1: sourceT[b,i,s] = sum_c conv_ctx_w[i,c] * context[b,c,s]  (R3-proven)
// ---------------------------------------------------------------------------
__global__ void __launch_bounds__(256) k1_sourceT(const float* __restrict__ ctx,
                                                  const float* __restrict__ w){
    const int b    = blockIdx.y;
    const int tid  = threadIdx.x;
    const int lane = tid & 31;
    const int i    = blockIdx.x * 8 + (tid >> 5);

    __shared__ float sctx[384*SL];     // 27 KB chunk of context[b]

    float acc[SL];
    #pragma unroll
    for (int s = 0; s < SL; ++s) acc[s] = 0.f;

    for (int c0 = 0; c0 < CDF; c0 += 384){
        __syncthreads();
        const float4* src = reinterpret_cast<const float4*>(ctx + (long long)b*CDF*SL + c0*SL);
        float4* dst = reinterpret_cast<float4*>(sctx);
        #pragma unroll
        for (int idx = tid; idx < 384*SL/4; idx += 256) dst[idx] = src[idx];
        __syncthreads();

        const float* wr = w + i*CDF + c0;
        #pragma unroll 4
        for (int j = 0; j < 12; ++j){
            const int c = lane + j*32;
            const float wv = __ldg(wr + c);
            const float* cp = &sctx[c*SL];
            #pragma unroll
            for (int s = 0; s < SL; ++s) acc[s] = fmaf(wv, cp[s], acc[s]);
        }
    }

    #pragma unroll
    for (int off = 16; off; off >>= 1){
        #pragma unroll
        for (int s = 0; s < SL; ++s)
            acc[s] += __shfl_xor_sync(0xffffffffu, acc[s], off);
    }
    if (lane == 0){
        #pragma unroll
        for (int s = 0; s < SL; ++s)
            g_sourceT[b*IDF*SL + i*SL + s] = acc[s];
    }
}

// ---------------------------------------------------------------------------
// k2: fused scores GEMV + softmax + cs-dot. This round: explicit MLP —
// burst-load 8 channels (8 back-to-back LDG.64) into a reg buffer, then
// consume. 2 q/thread, 3 CTAs/SM. grid (32 qtiles, 32 b).
// ---------------------------------------------------------------------------
__device__ __forceinline__ void k2_consume(const float2 xv, const float* rowf,
                                           unsigned long long* a0,
                                           unsigned long long* a1){
    unsigned long long t0 = pack2(xv.x, xv.x);
    unsigned long long t1 = pack2(xv.y, xv.y);
    const ulonglong2* r2 = reinterpret_cast<const ulonglong2*>(rowf);
    ulonglong2 v01 = r2[0];          // s0..s3
    ulonglong2 v23 = r2[1];          // s4..s7
    ulonglong2 v45 = r2[2];          // s8..s11
    ulonglong2 v67 = r2[3];          // s12..s15
    unsigned long long v8 = reinterpret_cast<const unsigned long long*>(rowf)[8]; // s16,s17
    ffma2(a0[0], t0, v01.x); ffma2(a1[0], t1, v01.x);
    ffma2(a0[1], t0, v01.y); ffma2(a1[1], t1, v01.y);
    ffma2(a0[2], t0, v23.x); ffma2(a1[2], t1, v23.x);
    ffma2(a0[3], t0, v23.y); ffma2(a1[3], t1, v23.y);
    ffma2(a0[4], t0, v45.x); ffma2(a1[4], t1, v45.x);
    ffma2(a0[5], t0, v45.y); ffma2(a1[5], t1, v45.y);
    ffma2(a0[6], t0, v67.x); ffma2(a1[6], t1, v67.x);
    ffma2(a0[7], t0, v67.y); ffma2(a1[7], t1, v67.y);
    ffma2(a0[8], t0, v8   ); ffma2(a1[8], t1, v8   );
}

__global__ void __launch_bounds__(256, 3) k2_attn(const float* __restrict__ x,
                                                  const float* __restrict__ conv_w,
                                                  const float* __restrict__ conv_b){
    const int b   = blockIdx.y;
    const int tid = threadIdx.x;

    __shared__ __align__(16) float ssrc[IDF*20];   // undup rows, stride 20 (80B)
    __shared__ float scs[SL];                       // cs[b,s]

    for (int idx = tid; idx < IDF*SL; idx += 256){
        int i = idx / SL, s = idx - i*SL;
        ssrc[i*20 + s] = g_sourceT[b*IDF*SL + idx];
    }
    __syncthreads();
    if (tid < SL){
        float c = 0.f;
        #pragma unroll 8
        for (int i = 0; i < IDF; ++i)
            c = fmaf(__ldg(conv_w + i), ssrc[i*20 + tid], c);
        scs[tid] = c;
    }
    __syncthreads();

    const int q0 = blockIdx.x * 512 + tid * 2;
    const float* xbase = x + (long long)b*IDF*QL + q0;

    unsigned long long a0[SP], a1[SP];
    #pragma unroll
    for (int p = 0; p < SP; ++p){ a0[p]=0ULL; a1[p]=0ULL; }

    #pragma unroll 1
    for (int c = 0; c < 8; ++c){
        const float* xc = xbase + (long long)c*8*QL;
        float2 buf[8];
        #pragma unroll
        for (int j = 0; j < 8; ++j)                 // 8 back-to-back LDG.64
            buf[j] = *reinterpret_cast<const float2*>(xc + (long long)j*QL);
        const float* rowc = ssrc + c*(8*20);
        #pragma unroll
        for (int j = 0; j < 8; ++j)
            k2_consume(buf[j], rowc + j*20, a0, a1);
    }

    // epilogue: softmax (max-free: |score| << 88) + cs dot
    float sa[SL], sb[SL];
    #pragma unroll
    for (int p = 0; p < SP; ++p){
        unpack2(a0[p], sa[2*p], sa[2*p+1]);
        unpack2(a1[p], sb[2*p], sb[2*p+1]);
    }
    float d0 = 0.f, d1 = 0.f, n0 = 0.f, n1 = 0.f;
    #pragma unroll
    for (int s = 0; s < SL; ++s){
        float e0 = __expf(sa[s]);
        float e1 = __expf(sb[s]);
        float cc = scs[s];
        d0 += e0; d1 += e1;
        n0 = fmaf(e0, cc, n0);
        n1 = fmaf(e1, cc, n1);
    }
    const float cb = conv_b[0];
    float2 o2 = make_float2(n0/d0 + cb, n1/d1 + cb);
    *reinterpret_cast<float2*>(&g_wctx2[b*QL + q0]) = o2;
}

// ---------------------------------------------------------------------------
// k3: split-K FC partials (R3-proven: coalesced [split][a][b] stores).
// ---------------------------------------------------------------------------
__global__ void __launch_bounds__(256) k3_fc(const float* __restrict__ fcw){
    const int split = blockIdx.x;
    const int k0    = split * KCH;
    const int tid   = threadIdx.x;
    const int lane  = tid & 31;
    const int w     = tid >> 5;

    __shared__ float sm[KCH*33];   // [k][b], padded (33.8 KB)
    for (int idx = tid; idx < BB*KCH; idx += 256){
        int b = idx >> 8;          // /256
        int k = idx & 255;
        sm[k*33 + b] = g_wctx2[b*QL + k0 + k];
    }
    __syncthreads();

    const int a0 = blockIdx.y * 16 + w * 2;   // a-pair {a0, a0+1}
    if (a0 >= ADIM) return;

    const float4* f0 = reinterpret_cast<const float4*>(fcw + (long long)(a0  )*QL + k0);
    const float4* f1 = reinterpret_cast<const float4*>(fcw + (long long)(a0+1)*QL + k0);
    float acc0 = 0.f, acc1 = 0.f;
    #pragma unroll 8
    for (int kq = 0; kq < KCH/4; ++kq){
        float4 x0 = __ldg(f0 + kq);
        float4 x1 = __ldg(f1 + kq);
        const int k = kq*4;
        float v0 = sm[(k+0)*33 + lane];
        float v1 = sm[(k+1)*33 + lane];
        float v2 = sm[(k+2)*33 + lane];
        float v3 = sm[(k+3)*33 + lane];
        acc0 = fmaf(x0.x, v0, acc0);  acc1 = fmaf(x1.x, v0, acc1);
        acc0 = fmaf(x0.y, v1, acc0);  acc1 = fmaf(x1.y, v1, acc1);
        acc0 = fmaf(x0.z, v2, acc0);  acc1 = fmaf(x1.z, v2, acc1);
        acc0 = fmaf(x0.w, v3, acc0);  acc1 = fmaf(x1.w, v3, acc1);
    }
    g_partial[split*(ADIM*BB) + (a0  )*BB + lane] = acc0;
    g_partial[split*(ADIM*BB) + (a0+1)*BB + lane] = acc1;
}

// ---------------------------------------------------------------------------
// k4: parallel reduce of split partials (R3-proven).
// ---------------------------------------------------------------------------
__global__ void __launch_bounds__(256) k4_reduce(const float* __restrict__ fcb,
                                                 float* __restrict__ out){
    const int a   = blockIdx.x;          // 0..99
    const int tid = threadIdx.x;
    const int b   = tid & 31;
    const int g   = tid >> 5;            // 0..7

    float acc = 0.f;
    #pragma unroll
    for (int sp = g; sp < NSPLIT; sp += 8)
        acc += g_partial[sp*(ADIM*BB) + a*BB + b];

    __shared__ float red[256];
    red[tid] = acc;
    __syncthreads();
    if (g == 0){
        float v = red[b] + red[b+32] + red[b+64] + red[b+96]
                + red[b+128] + red[b+160] + red[b+192] + red[b+224];
        out[b*ADIM + a] = v + fcb[a];
    }
}

extern "C" void kernel_launch(void* const* d_in, const int* in_sizes, int n_in,
                              void* d_out, int out_size){
    const float* inputs     = (const float*)d_in[0];  // [32,64,128,128]
    const float* context    = (const float*)d_in[1];  // [32,768,18]
    const float* conv_ctx_w = (const float*)d_in[2];  // [64,768]
    const float* conv_w     = (const float*)d_in[3];  // [64]
    const float* conv_b     = (const float*)d_in[4];  // [1]
    const float* fc_w       = (const float*)d_in[5];  // [100,16384]
    const float* fc_b       = (const float*)d_in[6];  // [100]
    float* out = (float*)d_out;                        // [32,100]

    k1_sourceT<<<dim3(8, BB), 256>>>(context, conv_ctx_w);
    k2_attn   <<<dim3(QL/512, BB), 256>>>(inputs, conv_w, conv_b);
    k3_fc     <<<dim3(NSPLIT, 7), 256>>>(fc_w);
    k4_reduce <<<ADIM, 256>>>(fc_b, out);
}